// round 1
// baseline (speedup 1.0000x reference)
#include <cuda_runtime.h>

// Problem constants
#define B_   64
#define T_   2048
#define DIN  128
#define H_   512
#define DOUT 128

// Tiling
#define TT  128   // timestep tile (GEMM M tile)
#define HT  128   // hidden tile   (GEMM N tile)
#define KC  16    // K chunk
#define TPB 256

// Scratch for inter-layer activations (static __device__ — allocation-free)
__device__ float g_h1[(size_t)B_ * T_ * H_];
__device__ float g_h2[(size_t)B_ * T_ * H_];

// Fused: proj = A @ W^T + (bl+bb), then per-channel scan h = relu(p + u*h),
// writing the hidden states directly (proj never hits DRAM).
// Block = (one batch b) x (HT hidden channels); walks T in TT tiles sequentially.
template <int K>
__global__ void __launch_bounds__(TPB, 2)
layer_kernel(const float* __restrict__ A,   // [B_, T_, K]
             const float* __restrict__ W,   // [H_, K]
             const float* __restrict__ bl,
             const float* __restrict__ u,
             const float* __restrict__ bb,
             float* __restrict__ Hout)      // [B_, T_, H_]
{
    __shared__ float As[KC][TT + 4];
    __shared__ float Ws[KC][HT + 4];
    __shared__ float state_s[HT];
    __shared__ float u_s[HT];
    __shared__ float bias_s[HT];

    const int h0  = blockIdx.x * HT;
    const int b   = blockIdx.y;
    const int tid = threadIdx.x;
    const int tx  = tid & 15;   // timestep group (16 groups of 8 t)
    const int ty  = tid >> 4;   // hidden group   (16 groups of 8 h)

    for (int i = tid; i < HT; i += TPB) {
        state_s[i] = 0.0f;
        u_s[i]     = u[h0 + i];
        bias_s[i]  = bl[h0 + i] + bb[h0 + i];
    }

    const float* Ab = A + (size_t)b * T_ * K;

    for (int t0 = 0; t0 < T_; t0 += TT) {
        float acc[8][8];
        #pragma unroll
        for (int i = 0; i < 8; i++)
            #pragma unroll
            for (int j = 0; j < 8; j++) acc[i][j] = 0.0f;

        for (int kc = 0; kc < K; kc += KC) {
            __syncthreads();
            // Load A tile [TT x KC] and W tile [HT x KC], transposed into smem.
            #pragma unroll
            for (int q = 0; q < 2; q++) {
                int idx = tid + q * TPB;       // 0..511
                int row = idx >> 2;            // 0..127
                int kq  = (idx & 3) << 2;      // 0,4,8,12
                float4 va = *(const float4*)&Ab[(size_t)(t0 + row) * K + kc + kq];
                As[kq + 0][row] = va.x; As[kq + 1][row] = va.y;
                As[kq + 2][row] = va.z; As[kq + 3][row] = va.w;
                float4 vw = *(const float4*)&W[(size_t)(h0 + row) * K + kc + kq];
                Ws[kq + 0][row] = vw.x; Ws[kq + 1][row] = vw.y;
                Ws[kq + 2][row] = vw.z; Ws[kq + 3][row] = vw.w;
            }
            __syncthreads();
            #pragma unroll
            for (int k = 0; k < KC; k++) {
                float a[8], w[8];
                *(float4*)&a[0] = *(const float4*)&As[k][tx * 8];
                *(float4*)&a[4] = *(const float4*)&As[k][tx * 8 + 4];
                *(float4*)&w[0] = *(const float4*)&Ws[k][ty * 8];
                *(float4*)&w[4] = *(const float4*)&Ws[k][ty * 8 + 4];
                #pragma unroll
                for (int i = 0; i < 8; i++)
                    #pragma unroll
                    for (int j = 0; j < 8; j++)
                        acc[i][j] += a[i] * w[j];
            }
        }
        __syncthreads();

        // Sequential scan: tx-group s handles timesteps [t0+8s, t0+8s+8).
        // State relays through smem; 8 independent dep-chains (one per j) for ILP.
        for (int s = 0; s < 16; s++) {
            if (tx == s) {
                #pragma unroll
                for (int j = 0; j < 8; j++) {
                    float hprev = state_s[ty * 8 + j];
                    float uu    = u_s[ty * 8 + j];
                    float bi    = bias_s[ty * 8 + j];
                    #pragma unroll
                    for (int i = 0; i < 8; i++) {
                        hprev = fmaxf(acc[i][j] + bi + uu * hprev, 0.0f);
                        acc[i][j] = hprev;
                    }
                    state_s[ty * 8 + j] = hprev;
                }
            }
            __syncthreads();
        }

        // Write hidden states
        float* Ob = Hout + ((size_t)b * T_ + t0) * H_ + h0;
        #pragma unroll
        for (int i = 0; i < 8; i++) {
            int r = tx * 8 + i;
            float4 v0 = make_float4(acc[i][0], acc[i][1], acc[i][2], acc[i][3]);
            float4 v1 = make_float4(acc[i][4], acc[i][5], acc[i][6], acc[i][7]);
            *(float4*)&Ob[(size_t)r * H_ + ty * 8]     = v0;
            *(float4*)&Ob[(size_t)r * H_ + ty * 8 + 4] = v1;
        }
    }
}

// Final FC: out[m, o] = sum_h h2[m, h] * fcW[o, h] + fcb[o]
// M = B_*T_ rows, N = DOUT = 128 (one block covers all N), K = H_ = 512.
__global__ void __launch_bounds__(TPB, 2)
fc_kernel(const float* __restrict__ A,     // [M, H_]
          const float* __restrict__ W,     // [DOUT, H_]
          const float* __restrict__ bias,  // [DOUT]
          float* __restrict__ out)         // [M, DOUT]
{
    __shared__ float As[KC][TT + 4];
    __shared__ float Ws[KC][HT + 4];

    const int m0  = blockIdx.x * TT;
    const int tid = threadIdx.x;
    const int tx  = tid & 15;
    const int ty  = tid >> 4;

    float acc[8][8];
    #pragma unroll
    for (int i = 0; i < 8; i++)
        #pragma unroll
        for (int j = 0; j < 8; j++) acc[i][j] = 0.0f;

    for (int kc = 0; kc < H_; kc += KC) {
        __syncthreads();
        #pragma unroll
        for (int q = 0; q < 2; q++) {
            int idx = tid + q * TPB;
            int row = idx >> 2;
            int kq  = (idx & 3) << 2;
            float4 va = *(const float4*)&A[(size_t)(m0 + row) * H_ + kc + kq];
            As[kq + 0][row] = va.x; As[kq + 1][row] = va.y;
            As[kq + 2][row] = va.z; As[kq + 3][row] = va.w;
            float4 vw = *(const float4*)&W[(size_t)row * H_ + kc + kq];
            Ws[kq + 0][row] = vw.x; Ws[kq + 1][row] = vw.y;
            Ws[kq + 2][row] = vw.z; Ws[kq + 3][row] = vw.w;
        }
        __syncthreads();
        #pragma unroll
        for (int k = 0; k < KC; k++) {
            float a[8], w[8];
            *(float4*)&a[0] = *(const float4*)&As[k][tx * 8];
            *(float4*)&a[4] = *(const float4*)&As[k][tx * 8 + 4];
            *(float4*)&w[0] = *(const float4*)&Ws[k][ty * 8];
            *(float4*)&w[4] = *(const float4*)&Ws[k][ty * 8 + 4];
            #pragma unroll
            for (int i = 0; i < 8; i++)
                #pragma unroll
                for (int j = 0; j < 8; j++)
                    acc[i][j] += a[i] * w[j];
        }
    }

    #pragma unroll
    for (int i = 0; i < 8; i++) {
        int m = m0 + tx * 8 + i;
        float* dst = out + (size_t)m * DOUT + ty * 8;
        #pragma unroll
        for (int j = 0; j < 8; j += 4) {
            float4 v = make_float4(acc[i][j + 0] + bias[ty * 8 + j + 0],
                                   acc[i][j + 1] + bias[ty * 8 + j + 1],
                                   acc[i][j + 2] + bias[ty * 8 + j + 2],
                                   acc[i][j + 3] + bias[ty * 8 + j + 3]);
            *(float4*)&dst[j] = v;
        }
    }
}

extern "C" void kernel_launch(void* const* d_in, const int* in_sizes, int n_in,
                              void* d_out, int out_size)
{
    const float* x   = (const float*)d_in[0];
    const float* W0  = (const float*)d_in[1];
    const float* bl0 = (const float*)d_in[2];
    const float* u0  = (const float*)d_in[3];
    const float* bb0 = (const float*)d_in[4];
    const float* W1  = (const float*)d_in[5];
    const float* bl1 = (const float*)d_in[6];
    const float* u1  = (const float*)d_in[7];
    const float* bb1 = (const float*)d_in[8];
    const float* fcW = (const float*)d_in[9];
    const float* fcb = (const float*)d_in[10];
    float* out = (float*)d_out;

    float *h1p, *h2p;
    cudaGetSymbolAddress((void**)&h1p, g_h1);
    cudaGetSymbolAddress((void**)&h2p, g_h2);

    dim3 lgrid(H_ / HT, B_);  // (4, 64)
    layer_kernel<DIN><<<lgrid, TPB>>>(x,   W0, bl0, u0, bb0, h1p);
    layer_kernel<H_> <<<lgrid, TPB>>>(h1p, W1, bl1, u1, bb1, h2p);
    fc_kernel<<<(B_ * T_) / TT, TPB>>>(h2p, fcW, fcb, out);
}

// round 3
// speedup vs baseline: 5.6272x; 5.6272x over previous
#include <cuda_runtime.h>
#include <cuda_bf16.h>
#include <cstdint>

#define B_   64
#define T_   2048
#define DIN  128
#define H_   512
#define DOUT 128

#define NT   128    // timestep tile (MMA N)
#define KC   64     // K elements per smem chunk (128 bytes bf16)
#define TPB  256

// ---- arch feature gate: tcgen05 only exists in the sm_103a/sm_100a pass ----
#if defined(__CUDA_ARCH__) && (defined(__CUDA_ARCH_FEAT_SM103_ALL) || defined(__CUDA_ARCH_FEAT_SM100_ALL))
#define USE_TC 1
#else
#define USE_TC 0
#endif

// idesc: dtype=F32(1<<4), atype=BF16(1<<7), btype=BF16(1<<10), N=128 (16<<17), M=128 (8<<24)
#define IDESC_128x128 0x8200490u

// SMEM layout (dynamic): [0:4) tmem ptr, [8:16) mbar, tiles at 1024 (1KB-aligned)
#define SM_WH 1024
#define SM_WL (1024 + 16384)
#define SM_XH (1024 + 2*16384)
#define SM_XL (1024 + 3*16384)
#define SM_TOTAL (1024 + 4*16384)

// ---------------- scratch (__device__ globals: allocation-free) ----------------
__device__ __nv_bfloat16 g_xhi[(size_t)B_ * T_ * DIN];
__device__ __nv_bfloat16 g_xlo[(size_t)B_ * T_ * DIN];
__device__ __nv_bfloat16 g_h1hi[(size_t)B_ * T_ * H_];
__device__ __nv_bfloat16 g_h1lo[(size_t)B_ * T_ * H_];
__device__ __nv_bfloat16 g_h2hi[(size_t)B_ * T_ * H_];
__device__ __nv_bfloat16 g_h2lo[(size_t)B_ * T_ * H_];
__device__ __nv_bfloat16 g_W0hi[H_ * DIN];
__device__ __nv_bfloat16 g_W0lo[H_ * DIN];
__device__ __nv_bfloat16 g_W1hi[H_ * H_];
__device__ __nv_bfloat16 g_W1lo[H_ * H_];
__device__ __nv_bfloat16 g_fWhi[DOUT * H_];
__device__ __nv_bfloat16 g_fWlo[DOUT * H_];

__device__ __forceinline__ float bsum(const __nv_bfloat16* hi, const __nv_bfloat16* lo, size_t i) {
    return __bfloat162float(hi[i]) + __bfloat162float(lo[i]);
}
__device__ __forceinline__ void bsplit(float v, __nv_bfloat16* hi, __nv_bfloat16* lo, size_t i) {
    __nv_bfloat16 h = __float2bfloat16(v);
    hi[i] = h;
    lo[i] = __float2bfloat16(v - __bfloat162float(h));
}

#if USE_TC
// ---------------- PTX helpers (sm_103a-only pass) ----------------
__device__ __forceinline__ uint32_t smem_to_u32(const void* p) {
    uint32_t a;
    asm("{ .reg .u64 t; cvta.to.shared.u64 t, %1; cvt.u32.u64 %0, t; }" : "=r"(a) : "l"(p));
    return a;
}
__device__ __forceinline__ uint32_t elect_one_pred() {
    uint32_t p;
    asm volatile("{\n\t.reg .pred p;\n\telect.sync _|p, 0xFFFFFFFF;\n\tselp.b32 %0, 1, 0, p;\n\t}" : "=r"(p));
    return p;
}
#define MBAR_INIT(a, c) asm volatile("mbarrier.init.shared.b64 [%0], %1;" :: "r"(a), "r"(c) : "memory")
#define MBAR_INVAL(a)   asm volatile("mbarrier.inval.shared.b64 [%0];" :: "r"(a) : "memory")
#define MBAR_WAIT(a, ph) do {                                                       \
    uint32_t _m = (a), _p = (ph), _d;                                               \
    asm volatile("{\n\t.reg .pred p;\n\t"                                           \
        "mbarrier.try_wait.parity.acquire.cta.shared::cta.b64 p, [%1], %2;\n\t"     \
        "selp.b32 %0, 1, 0, p;\n\t}" : "=r"(_d) : "r"(_m), "r"(_p) : "memory");     \
    if (!_d) {                                                                      \
        asm volatile("{\n\t.reg .pred P1;\n\tWL_%=:\n\t"                            \
            "mbarrier.try_wait.parity.acquire.cta.shared::cta.b64 P1, [%0], %1, 0x989680;\n\t" \
            "@P1 bra.uni WD_%=;\n\tbra.uni WL_%=;\n\tWD_%=:\n\t}"                   \
            :: "r"(_m), "r"(_p) : "memory");                                        \
    }                                                                               \
} while (0)
#define TC_ALLOC(sa, n)   asm volatile("tcgen05.alloc.cta_group::1.sync.aligned.shared::cta.b32 [%0], %1;" :: "r"(sa), "r"(n) : "memory")
#define TC_DEALLOC(t, n)  asm volatile("tcgen05.dealloc.cta_group::1.sync.aligned.b32 %0, %1;" :: "r"(t), "r"(n))
#define TC_RELINQ()       asm volatile("tcgen05.relinquish_alloc_permit.cta_group::1.sync.aligned;")
#define TC_COMMIT(mb)     asm volatile("tcgen05.commit.cta_group::1.mbarrier::arrive::one.shared::cluster.b64 [%0];" :: "r"(mb) : "memory")
#define TC_WAIT_LD()      asm volatile("tcgen05.wait::ld.sync.aligned;" ::: "memory")
#define TC_FENCE_BEFORE() asm volatile("tcgen05.fence::before_thread_sync;" ::: "memory")
#define TC_FENCE_AFTER()  asm volatile("tcgen05.fence::after_thread_sync;" ::: "memory")
#define FENCE_ASYNC()     asm volatile("fence.proxy.async.shared::cta;" ::: "memory")

__device__ __forceinline__ void mma_f16_ss(uint32_t d, uint64_t ad, uint64_t bd,
                                           uint32_t idesc, uint32_t en) {
    asm volatile(
        "{\n\t.reg .pred p;\n\tsetp.ne.u32 p, %5, 0;\n\t"
        "tcgen05.mma.cta_group::1.kind::f16 [%0], %1, %2, %3, {%4, %4, %4, %4}, p;\n\t}"
        :: "r"(d), "l"(ad), "l"(bd), "r"(idesc), "r"(0u), "r"(en) : "memory");
}

// SW128 desc: layout=2, version=1, SBO=64, LBO=1 (128B rows, 8-row atoms)
__device__ __forceinline__ uint64_t mk_desc(uint32_t addr) {
    return ((uint64_t)2 << 61) | ((uint64_t)1 << 46) | ((uint64_t)64 << 32)
         | ((uint64_t)1 << 16) | ((uint64_t)(addr >> 4) & 0x3FFF);
}

#define LDTM_X32(r, a)                                                              \
    asm volatile("tcgen05.ld.sync.aligned.32x32b.x32.b32 "                          \
        "{%0,%1,%2,%3,%4,%5,%6,%7,%8,%9,%10,%11,%12,%13,%14,%15,"                   \
        "%16,%17,%18,%19,%20,%21,%22,%23,%24,%25,%26,%27,%28,%29,%30,%31}, [%32];"  \
        : "=r"((r)[0]),"=r"((r)[1]),"=r"((r)[2]),"=r"((r)[3]),                       \
          "=r"((r)[4]),"=r"((r)[5]),"=r"((r)[6]),"=r"((r)[7]),                       \
          "=r"((r)[8]),"=r"((r)[9]),"=r"((r)[10]),"=r"((r)[11]),                     \
          "=r"((r)[12]),"=r"((r)[13]),"=r"((r)[14]),"=r"((r)[15]),                   \
          "=r"((r)[16]),"=r"((r)[17]),"=r"((r)[18]),"=r"((r)[19]),                   \
          "=r"((r)[20]),"=r"((r)[21]),"=r"((r)[22]),"=r"((r)[23]),                   \
          "=r"((r)[24]),"=r"((r)[25]),"=r"((r)[26]),"=r"((r)[27]),                   \
          "=r"((r)[28]),"=r"((r)[29]),"=r"((r)[30]),"=r"((r)[31]) : "r"(a))

// ---------------- chunk loader: 4 tiles of [128 rows x 64 bf16], SW128 ----------------
__device__ __forceinline__ void load_chunk(char* smem,
        const __nv_bfloat16* Ahi, const __nv_bfloat16* Alo, size_t arow0,
        const __nv_bfloat16* Bhi, const __nv_bfloat16* Blo, size_t brow0,
        int K, int kc, int tid) {
    const int tile = tid >> 6;        // 0..3
    const int ltid = tid & 63;
    const int j = ltid & 7;           // 16B column within row
    const int rb = ltid >> 3;         // row sub (0..7)
    const __nv_bfloat16* base;
    size_t row0;
    if (tile == 0)      { base = Ahi; row0 = arow0; }
    else if (tile == 1) { base = Alo; row0 = arow0; }
    else if (tile == 2) { base = Bhi; row0 = brow0; }
    else                { base = Blo; row0 = brow0; }
    char* stile = smem + SM_WH + tile * 16384;
    #pragma unroll
    for (int p = 0; p < 16; p++) {
        int r = rb + p * 8;
        const uint4* src = (const uint4*)(base + (row0 + r) * K + kc);
        uint4 v = __ldg(&src[j]);
        uint32_t off = r * 128 + j * 16;
        uint32_t sw = off ^ ((off >> 3) & 0x70);
        *(uint4*)(stile + sw) = v;
    }
}
#endif  // USE_TC

// ---------------- fp32 -> bf16 hi/lo split ----------------
__global__ void split_kernel(const float* __restrict__ src,
                             __nv_bfloat16* __restrict__ hi,
                             __nv_bfloat16* __restrict__ lo, int n) {
    for (int i = blockIdx.x * blockDim.x + threadIdx.x; i < n; i += gridDim.x * blockDim.x) {
        float v = src[i];
        __nv_bfloat16 h = __float2bfloat16(v);
        hi[i] = h;
        lo[i] = __float2bfloat16(v - __bfloat162float(h));
    }
}

// ---------------- fused layer: GEMM + per-channel scan ----------------
// grid (H_/128, B_), block 256. D[h lanes, t cols]; thread tid<128 owns channel h0+tid.
template <int K>
__global__ void __launch_bounds__(TPB, 1)
layer_tc(const __nv_bfloat16* __restrict__ Xhi, const __nv_bfloat16* __restrict__ Xlo,
         const __nv_bfloat16* __restrict__ Whi, const __nv_bfloat16* __restrict__ Wlo,
         const float* __restrict__ bl, const float* __restrict__ u, const float* __restrict__ bb,
         __nv_bfloat16* __restrict__ Hhi, __nv_bfloat16* __restrict__ Hlo) {
    extern __shared__ char smem[];
    const int tid = threadIdx.x;
    const int h0 = blockIdx.x * 128;
    const int b  = blockIdx.y;
#if USE_TC
    const uint32_t smb = smem_to_u32(smem);
    const int wid = tid >> 5;

    if (tid == 0) MBAR_INIT(smb + 8, 1);
    if (wid == 0) { TC_ALLOC(smb, 128); TC_RELINQ(); }
    __syncthreads();
    uint32_t tmem;
    asm volatile("ld.shared.b32 %0, [%1];" : "=r"(tmem) : "r"(smb));

    float hcar = 0.0f, uu = 0.0f, bi = 0.0f;
    if (tid < 128) { uu = u[h0 + tid]; bi = bl[h0 + tid] + bb[h0 + tid]; }

    const uint64_t dWh = mk_desc(smb + SM_WH), dWl = mk_desc(smb + SM_WL);
    const uint64_t dXh = mk_desc(smb + SM_XH), dXl = mk_desc(smb + SM_XL);
    int phase = 0;

    for (int t0 = 0; t0 < T_; t0 += NT) {
        for (int kc = 0; kc < K; kc += KC) {
            __syncthreads();
            load_chunk(smem, Whi, Wlo, (size_t)h0, Xhi, Xlo, (size_t)b * T_ + t0, K, kc, tid);
            __syncthreads();
            if (wid == 0) {
                FENCE_ASYNC();
                if (elect_one_pred()) {
                    uint32_t en0 = (kc == 0) ? 0u : 1u;
                    #pragma unroll
                    for (int k = 0; k < 4; k++) {
                        uint64_t off = (uint64_t)(k * 2);
                        mma_f16_ss(tmem, dWh + off, dXh + off, IDESC_128x128, (k == 0) ? en0 : 1u);
                        mma_f16_ss(tmem, dWh + off, dXl + off, IDESC_128x128, 1u);
                        mma_f16_ss(tmem, dWl + off, dXh + off, IDESC_128x128, 1u);
                    }
                    TC_COMMIT(smb + 8);
                }
            }
            MBAR_WAIT(smb + 8, phase);
            phase ^= 1;
        }
        if (tid < 128) {
            TC_FENCE_AFTER();
            #pragma unroll
            for (int cb = 0; cb < 4; cb++) {
                uint32_t d[32];
                LDTM_X32(d, tmem + cb * 32);
                TC_WAIT_LD();
                size_t obase = ((size_t)b * T_ + (t0 + cb * 32)) * H_ + h0 + tid;
                #pragma unroll
                for (int i = 0; i < 32; i++) {
                    float p = __uint_as_float(d[i]) + bi;
                    hcar = fmaxf(fmaf(uu, hcar, p), 0.0f);
                    bsplit(hcar, Hhi, Hlo, obase + (size_t)i * H_);
                }
            }
            TC_FENCE_BEFORE();
        }
        __syncthreads();
    }
    if (wid == 0) {
        if (elect_one_pred()) MBAR_INVAL(smb + 8);
        TC_DEALLOC(tmem, 128);
    }
#else
    // SIMT fallback (runs only if the non-arch-specific image is loaded).
    // Thread tid<128 owns channel h0+tid; X row staged in smem per timestep.
    float* xrow  = (float*)smem;                 // K floats
    float hcar = 0.0f;
    float uu = 0.0f, bi = 0.0f;
    if (tid < 128) { uu = u[h0 + tid]; bi = bl[h0 + tid] + bb[h0 + tid]; }
    const __nv_bfloat16* wh = Whi + (size_t)(h0 + (tid < 128 ? tid : 0)) * K;
    const __nv_bfloat16* wl = Wlo + (size_t)(h0 + (tid < 128 ? tid : 0)) * K;
    for (int t = 0; t < T_; t++) {
        __syncthreads();
        size_t xr = ((size_t)b * T_ + t) * K;
        for (int i = tid; i < K; i += TPB) xrow[i] = bsum(Xhi, Xlo, xr + i);
        __syncthreads();
        if (tid < 128) {
            float acc = 0.0f;
            for (int k = 0; k < K; k++)
                acc += (__bfloat162float(wh[k]) + __bfloat162float(wl[k])) * xrow[k];
            hcar = fmaxf(acc + bi + uu * hcar, 0.0f);
            bsplit(hcar, Hhi, Hlo, ((size_t)b * T_ + t) * H_ + h0 + tid);
        }
    }
#endif
}

// ---------------- FC: out[b,t,o] = h2[b,t,:] . fcW[o,:] + fcb[o] ----------------
// grid (T_/NT, B_), block 256.
__global__ void __launch_bounds__(TPB, 1)
fc_tc(const __nv_bfloat16* __restrict__ Xhi, const __nv_bfloat16* __restrict__ Xlo,
      const __nv_bfloat16* __restrict__ Whi, const __nv_bfloat16* __restrict__ Wlo,
      const float* __restrict__ bias, float* __restrict__ out) {
    extern __shared__ char smem[];
    const int tid = threadIdx.x;
    const int t0 = blockIdx.x * NT;
    const int b  = blockIdx.y;
#if USE_TC
    const uint32_t smb = smem_to_u32(smem);
    const int wid = tid >> 5;

    if (tid == 0) MBAR_INIT(smb + 8, 1);
    if (wid == 0) { TC_ALLOC(smb, 128); TC_RELINQ(); }
    __syncthreads();
    uint32_t tmem;
    asm volatile("ld.shared.b32 %0, [%1];" : "=r"(tmem) : "r"(smb));

    const uint64_t dWh = mk_desc(smb + SM_WH), dWl = mk_desc(smb + SM_WL);
    const uint64_t dXh = mk_desc(smb + SM_XH), dXl = mk_desc(smb + SM_XL);
    int phase = 0;

    for (int kc = 0; kc < H_; kc += KC) {
        __syncthreads();
        load_chunk(smem, Whi, Wlo, (size_t)0, Xhi, Xlo, (size_t)b * T_ + t0, H_, kc, tid);
        __syncthreads();
        if (wid == 0) {
            FENCE_ASYNC();
            if (elect_one_pred()) {
                uint32_t en0 = (kc == 0) ? 0u : 1u;
                #pragma unroll
                for (int k = 0; k < 4; k++) {
                    uint64_t off = (uint64_t)(k * 2);
                    mma_f16_ss(tmem, dWh + off, dXh + off, IDESC_128x128, (k == 0) ? en0 : 1u);
                    mma_f16_ss(tmem, dWh + off, dXl + off, IDESC_128x128, 1u);
                    mma_f16_ss(tmem, dWl + off, dXh + off, IDESC_128x128, 1u);
                }
                TC_COMMIT(smb + 8);
            }
        }
        MBAR_WAIT(smb + 8, phase);
        phase ^= 1;
    }
    if (tid < 128) {        // lane = output channel o
        TC_FENCE_AFTER();
        const float bo = bias[tid];
        #pragma unroll
        for (int cb = 0; cb < 4; cb++) {
            uint32_t d[32];
            LDTM_X32(d, tmem + cb * 32);
            TC_WAIT_LD();
            size_t obase = ((size_t)b * T_ + (t0 + cb * 32)) * DOUT + tid;
            #pragma unroll
            for (int i = 0; i < 32; i++)
                out[obase + (size_t)i * DOUT] = __uint_as_float(d[i]) + bo;
        }
        TC_FENCE_BEFORE();
    }
    __syncthreads();
    if (wid == 0) {
        if (elect_one_pred()) MBAR_INVAL(smb + 8);
        TC_DEALLOC(tmem, 128);
    }
#else
    // SIMT fallback: thread tid<128 owns output channel o=tid.
    float* xrow = (float*)smem;   // H_ floats
    const __nv_bfloat16* wh = Whi + (size_t)(tid < 128 ? tid : 0) * H_;
    const __nv_bfloat16* wl = Wlo + (size_t)(tid < 128 ? tid : 0) * H_;
    float bo = (tid < 128) ? bias[tid] : 0.0f;
    for (int tt = 0; tt < NT; tt++) {
        __syncthreads();
        size_t xr = ((size_t)b * T_ + t0 + tt) * H_;
        for (int i = tid; i < H_; i += TPB) xrow[i] = bsum(Xhi, Xlo, xr + i);
        __syncthreads();
        if (tid < 128) {
            float acc = 0.0f;
            for (int k = 0; k < H_; k++)
                acc += (__bfloat162float(wh[k]) + __bfloat162float(wl[k])) * xrow[k];
            out[((size_t)b * T_ + t0 + tt) * DOUT + tid] = acc + bo;
        }
    }
#endif
}

extern "C" void kernel_launch(void* const* d_in, const int* in_sizes, int n_in,
                              void* d_out, int out_size) {
    const float* x   = (const float*)d_in[0];
    const float* W0  = (const float*)d_in[1];
    const float* bl0 = (const float*)d_in[2];
    const float* u0  = (const float*)d_in[3];
    const float* bb0 = (const float*)d_in[4];
    const float* W1  = (const float*)d_in[5];
    const float* bl1 = (const float*)d_in[6];
    const float* u1  = (const float*)d_in[7];
    const float* bb1 = (const float*)d_in[8];
    const float* fcW = (const float*)d_in[9];
    const float* fcb = (const float*)d_in[10];
    float* out = (float*)d_out;

    __nv_bfloat16 *xhi, *xlo, *h1hi, *h1lo, *h2hi, *h2lo;
    __nv_bfloat16 *w0hi, *w0lo, *w1hi, *w1lo, *fwhi, *fwlo;
    cudaGetSymbolAddress((void**)&xhi,  g_xhi);
    cudaGetSymbolAddress((void**)&xlo,  g_xlo);
    cudaGetSymbolAddress((void**)&h1hi, g_h1hi);
    cudaGetSymbolAddress((void**)&h1lo, g_h1lo);
    cudaGetSymbolAddress((void**)&h2hi, g_h2hi);
    cudaGetSymbolAddress((void**)&h2lo, g_h2lo);
    cudaGetSymbolAddress((void**)&w0hi, g_W0hi);
    cudaGetSymbolAddress((void**)&w0lo, g_W0lo);
    cudaGetSymbolAddress((void**)&w1hi, g_W1hi);
    cudaGetSymbolAddress((void**)&w1lo, g_W1lo);
    cudaGetSymbolAddress((void**)&fwhi, g_fWhi);
    cudaGetSymbolAddress((void**)&fwlo, g_fWlo);

    cudaFuncSetAttribute(layer_tc<DIN>, cudaFuncAttributeMaxDynamicSharedMemorySize, SM_TOTAL);
    cudaFuncSetAttribute(layer_tc<H_>,  cudaFuncAttributeMaxDynamicSharedMemorySize, SM_TOTAL);
    cudaFuncSetAttribute(fc_tc,         cudaFuncAttributeMaxDynamicSharedMemorySize, SM_TOTAL);

    split_kernel<<<1024, 256>>>(x,   xhi,  xlo,  B_ * T_ * DIN);
    split_kernel<<<64,   256>>>(W0,  w0hi, w0lo, H_ * DIN);
    split_kernel<<<256,  256>>>(W1,  w1hi, w1lo, H_ * H_);
    split_kernel<<<64,   256>>>(fcW, fwhi, fwlo, DOUT * H_);

    dim3 lgrid(H_ / 128, B_);          // (4, 64)
    layer_tc<DIN><<<lgrid, TPB, SM_TOTAL>>>(xhi, xlo, w0hi, w0lo, bl0, u0, bb0, h1hi, h1lo);
    layer_tc<H_> <<<lgrid, TPB, SM_TOTAL>>>(h1hi, h1lo, w1hi, w1lo, bl1, u1, bb1, h2hi, h2lo);
    dim3 fgrid(T_ / NT, B_);           // (16, 64)
    fc_tc<<<fgrid, TPB, SM_TOTAL>>>(h2hi, h2lo, fwhi, fwlo, fcb, out);
}